// round 4
// baseline (speedup 1.0000x reference)
#include <cuda_runtime.h>

#define BATCH 2
#define DIM   256
#define HEADS 8
#define HD    32
#define RES   256
#define FWS   8
#define BN    512            // BATCH * 16 * 16 windows
#define NPIX  64
#define ATTN_SCALE 0.17677669529663689f

// ---------------- device scratch (static allocation is allowed) ----------------
__device__ float g_sub[(size_t)4 * BN * DIM * NPIX];   // [s][w][c][n]  134.2 MB
__device__ float g_bias[HEADS * NPIX * NPIX];          // gathered bias  128 KB

typedef unsigned long long u64;

__device__ __forceinline__ u64 pack2(float lo, float hi) {
    u64 r; asm("mov.b64 %0,{%1,%2};" : "=l"(r) : "f"(lo), "f"(hi)); return r;
}
__device__ __forceinline__ void unpack2(u64 v, float& a, float& b) {
    asm("mov.b64 {%0,%1},%2;" : "=f"(a), "=f"(b) : "l"(v));
}
__device__ __forceinline__ void fma2(u64& d, u64 a, u64 b) {
    asm("fma.rn.f32x2 %0,%1,%2,%0;" : "+l"(d) : "l"(a), "l"(b));
}

// ---------------- bias gather: g_bias[i][n][m] = ab[i][idxs[n*64+m]] ----------
__global__ void wwa_bias(const float* __restrict__ ab, const int* __restrict__ idxs, int n_off) {
    int idx = blockIdx.x * 256 + threadIdx.x;      // 0..32767
    int i = idx >> 12, r = idx & 4095;
    g_bias[idx] = ab[i * n_off + idxs[r]];
}

// ---------------- wavelet transform: 2x2 stride-2 depthwise, 4 subbands ------
// one thread per (window, channel, horizontal pixel-pair)
__global__ void wwa_wt(const float* __restrict__ x, const float* __restrict__ wf) {
    int g = blockIdx.x * 256 + threadIdx.x;        // < 512*256*32 = 4194304
    int pair = g & 31;
    int c = (g >> 5) & 255;
    int w = g >> 13;
    int b = w >> 8, wy = (w >> 4) & 15, wx = w & 15;
    int n0 = pair * 2;                              // even pixel index in window
    int p = wy * 8 + (n0 >> 3);
    int q0 = wx * 8 + (n0 & 7);                     // even
    const float* xp = x + ((size_t)(b * DIM + c) * RES + 2 * p) * RES + 2 * q0;
    float4 r0 = *(const float4*)xp;
    float4 r1 = *(const float4*)(xp + RES);
    const float4* wf4 = (const float4*)wf;          // wt_filter[(4c+s)] as float4
    float* dst = g_sub + ((size_t)w * DIM + c) * NPIX + n0;
#pragma unroll
    for (int s = 0; s < 4; s++) {
        float4 f = wf4[4 * c + s];                  // w00,w01,w10,w11
        float o0 = r0.x * f.x + r0.y * f.y + r1.x * f.z + r1.y * f.w;
        float o1 = r0.z * f.x + r0.w * f.y + r1.z * f.z + r1.w * f.w;
        *(float2*)(dst + (size_t)s * BN * DIM * NPIX) = make_float2(o0, o1);
    }
}

// ---------------- main: attention cascade + projection + inverse WT ----------
// smem float offsets
#define S_OUT  0                     // cat (relu'd)     [256][68]  = 17408
#define S_V    17408                 // running ll_i     [32][66]   =  2112
#define S_K    19520                 // k slice          [32][66]   =  2112
#define S_TMP  21632                 // raw attn out     [32][66]   =  2112
#define S_ATTN 23744                 // softmax probs    [64][68]   =  4352
#define S_Q    28096                 // q (n-major)      [64][33]   =  2112
#define S_LH   30208                 // padded conv tile [32][145]  =  4640
#define S_DWW  34848                 // conv weights     [32][25]   =   800
#define S_DWB  35648                 // conv bias        [32]
#define SMEM_FLOATS 35680
#define SMEM_BYTES  (SMEM_FLOATS * 4)

__global__ __launch_bounds__(256, 1)
void wwa_main(const float* __restrict__ dww, const float* __restrict__ dwb,
              const float* __restrict__ pw,  const float* __restrict__ pbias,
              const float* __restrict__ iwt, float* __restrict__ out) {
    extern __shared__ float sm[];
    const int t = threadIdx.x;
    const int w = blockIdx.x;
    const int b = w >> 8, wy = (w >> 4) & 15, wx = w & 15;
    const float* subw0 = g_sub + (size_t)w * DIM * NPIX;                          // ll
    const float* subw1 = g_sub + ((size_t)BN + w) * DIM * NPIX;                   // lh
    const float* subw2 = g_sub + ((size_t)2 * BN + w) * DIM * NPIX;               // hl
    const float* subw3 = g_sub + ((size_t)3 * BN + w) * DIM * NPIX;               // hh

    // zero padded conv tile once (halo stays zero across heads)
    for (int k = t; k < 32 * 145; k += 256) sm[S_LH + k] = 0.f;
    // v = ll slice 0
    for (int k = t; k < 2048; k += 256) {
        int c = k >> 6, n = k & 63;
        sm[S_V + c * 66 + n] = subw0[k];
    }

#pragma unroll 1
    for (int i = 0; i < 8; i++) {
        __syncthreads();
        const float* llp = subw0 + i * HD * NPIX;
        const float* lhp = subw1 + i * HD * NPIX;
        const float* hlp = subw2 + i * HD * NPIX;
        if (i > 0) {
            for (int k = t; k < 2048; k += 256) {
                int c = k >> 6, n = k & 63;
                sm[S_V + c * 66 + n] = sm[S_TMP + c * 66 + n] + llp[k];
            }
        }
        for (int k = t; k < 2048; k += 256) {
            int c = k >> 6, n = k & 63;
            sm[S_LH + c * 145 + (n >> 3) * 12 + (n & 7) + 26] = lhp[k];  // (+2,+2) pad
            sm[S_K + c * 66 + n] = hlp[k];
        }
        for (int k = t; k < 800; k += 256) sm[S_DWW + k] = dww[i * 800 + k];
        if (t < 32) sm[S_DWB + t] = dwb[i * 32 + t];
        __syncthreads();

        // --- depthwise 5x5 conv (pad 2) -> q[n][d] ---
        {
            int d = t & 31, py = t >> 5;
            float wl[25];
#pragma unroll
            for (int k = 0; k < 25; k++) wl[k] = sm[S_DWW + d * 25 + k];
            float bb = sm[S_DWB + d];
            const float* base = &sm[S_LH + d * 145 + py * 12];
#pragma unroll
            for (int qx = 0; qx < 8; qx++) {
                float acc = bb;
#pragma unroll
                for (int ii = 0; ii < 5; ii++)
#pragma unroll
                    for (int jj = 0; jj < 5; jj++)
                        acc += base[ii * 12 + qx + jj] * wl[ii * 5 + jj];
                sm[S_Q + (py * 8 + qx) * 33 + d] = acc;
            }
        }
        __syncthreads();

        // --- attn = softmax(q k^T * scale + bias) ---
        {
            int rg = t >> 4, cg = t & 15, m0 = cg * 4;
            u64 acc[4][2] = {};
#pragma unroll 4
            for (int d = 0; d < 32; d++) {
                u64 k0 = *(const u64*)&sm[S_K + d * 66 + m0];
                u64 k1 = *(const u64*)&sm[S_K + d * 66 + m0 + 2];
#pragma unroll
                for (int r = 0; r < 4; r++) {
                    float qv = sm[S_Q + (rg * 4 + r) * 33 + d];
                    u64 q2 = pack2(qv, qv);
                    fma2(acc[r][0], q2, k0);
                    fma2(acc[r][1], q2, k1);
                }
            }
#pragma unroll
            for (int r = 0; r < 4; r++) {
                int n = rg * 4 + r;
                float v0, v1, v2, v3;
                unpack2(acc[r][0], v0, v1);
                unpack2(acc[r][1], v2, v3);
                const float4 bv = *(const float4*)&g_bias[i * 4096 + n * 64 + m0];
                v0 = v0 * ATTN_SCALE + bv.x; v1 = v1 * ATTN_SCALE + bv.y;
                v2 = v2 * ATTN_SCALE + bv.z; v3 = v3 * ATTN_SCALE + bv.w;
                float mx = fmaxf(fmaxf(v0, v1), fmaxf(v2, v3));
#pragma unroll
                for (int off = 8; off >= 1; off >>= 1)
                    mx = fmaxf(mx, __shfl_xor_sync(0xffffffffu, mx, off));
                v0 = __expf(v0 - mx); v1 = __expf(v1 - mx);
                v2 = __expf(v2 - mx); v3 = __expf(v3 - mx);
                float s = v0 + v1 + v2 + v3;
#pragma unroll
                for (int off = 8; off >= 1; off >>= 1)
                    s += __shfl_xor_sync(0xffffffffu, s, off);
                float inv = __fdividef(1.f, s);
                *(float4*)&sm[S_ATTN + n * 68 + m0] =
                    make_float4(v0 * inv, v1 * inv, v2 * inv, v3 * inv);
            }
        }
        __syncthreads();

        // --- out[d][n] = sum_m v[d][m] * attn[n][m] ---
        {
            int d = t & 31, nb = (t >> 5) * 8;
            u64 acc[8] = {};
#pragma unroll 4
            for (int m = 0; m < 64; m += 2) {
                u64 vv = *(const u64*)&sm[S_V + d * 66 + m];
#pragma unroll
                for (int j = 0; j < 8; j++)
                    fma2(acc[j], vv, *(const u64*)&sm[S_ATTN + (nb + j) * 68 + m]);
            }
#pragma unroll
            for (int j = 0; j < 8; j++) {
                float lo, hi; unpack2(acc[j], lo, hi);
                float val = lo + hi;
                sm[S_TMP + d * 66 + nb + j] = val;                  // next head's v base
                sm[S_OUT + (i * 32 + d) * 68 + nb + j] = fmaxf(val, 0.f);  // relu'd cat
            }
        }
    }
    __syncthreads();

    // --- projection (o = t) fused with inverse WT ---
    {
        int o = t;
        float pbv = pbias[o];
        u64 acc[32];
        u64 pinit = pack2(pbv, pbv);
#pragma unroll
        for (int u = 0; u < 32; u++) acc[u] = pinit;
        const float* wrow = pw + o * 256;
#pragma unroll 2
        for (int c = 0; c < 256; c++) {
            float wv = __ldg(&wrow[c]);
            u64 w2 = pack2(wv, wv);
            const u64* row = (const u64*)&sm[S_OUT + c * 68];
#pragma unroll
            for (int u = 0; u < 32; u++) fma2(acc[u], w2, row[u]);
        }
        const float4* iw4 = (const float4*)iwt;     // iwt_filter[(4o+s)] as float4
        float4 f0 = iw4[4 * o + 0], f1 = iw4[4 * o + 1];
        float4 f2 = iw4[4 * o + 2], f3 = iw4[4 * o + 3];
        const float* lhp = subw1 + o * NPIX;
        const float* hlp = subw2 + o * NPIX;
        const float* hhp = subw3 + o * NPIX;
        float* op = out + (size_t)(b * DIM + o) * RES * RES;
        int ybase = wy * 16, xbase = wx * 16;
#pragma unroll 2
        for (int u = 0; u < 32; u++) {
            int n0 = 2 * u;
            float a0, a1; unpack2(acc[u], a0, a1);
            int py = n0 >> 3, qx = n0 & 7;
            int y0 = ybase + 2 * py, x0 = xbase + 2 * qx;
            float2 lh2 = *(const float2*)&lhp[n0];
            float2 hl2 = *(const float2*)&hlp[n0];
            float2 hh2 = *(const float2*)&hhp[n0];
            float4 r0, r1;
            r0.x = a0 * f0.x + lh2.x * f1.x + hl2.x * f2.x + hh2.x * f3.x;
            r0.y = a0 * f0.y + lh2.x * f1.y + hl2.x * f2.y + hh2.x * f3.y;
            r1.x = a0 * f0.z + lh2.x * f1.z + hl2.x * f2.z + hh2.x * f3.z;
            r1.y = a0 * f0.w + lh2.x * f1.w + hl2.x * f2.w + hh2.x * f3.w;
            r0.z = a1 * f0.x + lh2.y * f1.x + hl2.y * f2.x + hh2.y * f3.x;
            r0.w = a1 * f0.y + lh2.y * f1.y + hl2.y * f2.y + hh2.y * f3.y;
            r1.z = a1 * f0.z + lh2.y * f1.z + hl2.y * f2.z + hh2.y * f3.z;
            r1.w = a1 * f0.w + lh2.y * f1.w + hl2.y * f2.w + hh2.y * f3.w;
            *(float4*)&op[(size_t)y0 * RES + x0] = r0;
            *(float4*)&op[(size_t)(y0 + 1) * RES + x0] = r1;
        }
    }
}

extern "C" void kernel_launch(void* const* d_in, const int* in_sizes, int n_in,
                              void* d_out, int out_size) {
    const float* x    = (const float*)d_in[0];
    const float* wtf  = (const float*)d_in[1];
    const float* iwtf = (const float*)d_in[2];
    const float* dww  = (const float*)d_in[3];
    const float* dwb  = (const float*)d_in[4];
    const float* pw   = (const float*)d_in[5];
    const float* pb   = (const float*)d_in[6];
    const float* ab   = (const float*)d_in[7];
    const int*   idxs = (const int*)d_in[8];
    int n_off = in_sizes[7] / HEADS;
    float* out = (float*)d_out;

    cudaFuncSetAttribute(wwa_main, cudaFuncAttributeMaxDynamicSharedMemorySize, SMEM_BYTES);

    wwa_bias<<<128, 256>>>(ab, idxs, n_off);
    wwa_wt<<<16384, 256>>>(x, wtf);
    wwa_main<<<512, 256, SMEM_BYTES>>>(dww, dwb, pw, pb, iwtf, out);
}

// round 5
// speedup vs baseline: 1.3903x; 1.3903x over previous
#include <cuda_runtime.h>

#define BATCH 2
#define DIM   256
#define HEADS 8
#define HD    32
#define RES   256
#define FWS   8
#define BN    512            // BATCH * 16 * 16 windows
#define NPIX  64
#define ATTN_SCALE 0.17677669529663689f

// ---------------- device scratch ----------------
__device__ float g_sub[(size_t)4 * BN * DIM * NPIX];          // [s][w][c][n]  134.2 MB
__device__ float g_bias[HEADS * NPIX * NPIX];                 // 128 KB
__device__ float g_attn[(size_t)BN * HEADS * NPIX * NPIX];    // softmaxed attn, 67 MB

typedef unsigned long long u64;

__device__ __forceinline__ u64 pack2(float lo, float hi) {
    u64 r; asm("mov.b64 %0,{%1,%2};" : "=l"(r) : "f"(lo), "f"(hi)); return r;
}
__device__ __forceinline__ void unpack2(u64 v, float& a, float& b) {
    asm("mov.b64 {%0,%1},%2;" : "=f"(a), "=f"(b) : "l"(v));
}
__device__ __forceinline__ void fma2(u64& d, u64 a, u64 b) {
    asm("fma.rn.f32x2 %0,%1,%2,%0;" : "+l"(d) : "l"(a), "l"(b));
}

// ---------------- bias gather ----------------
__global__ void wwa_bias(const float* __restrict__ ab, const int* __restrict__ idxs, int n_off) {
    int idx = blockIdx.x * 256 + threadIdx.x;      // 0..32767
    int i = idx >> 12, r = idx & 4095;
    g_bias[idx] = ab[i * n_off + idxs[r]];
}

// ---------------- wavelet transform ----------------
__global__ void wwa_wt(const float* __restrict__ x, const float* __restrict__ wf) {
    int g = blockIdx.x * 256 + threadIdx.x;
    int pair = g & 31;
    int c = (g >> 5) & 255;
    int w = g >> 13;
    int b = w >> 8, wy = (w >> 4) & 15, wx = w & 15;
    int n0 = pair * 2;
    int p = wy * 8 + (n0 >> 3);
    int q0 = wx * 8 + (n0 & 7);
    const float* xp = x + ((size_t)(b * DIM + c) * RES + 2 * p) * RES + 2 * q0;
    float4 r0 = *(const float4*)xp;
    float4 r1 = *(const float4*)(xp + RES);
    const float4* wf4 = (const float4*)wf;
    float* dst = g_sub + ((size_t)w * DIM + c) * NPIX + n0;
#pragma unroll
    for (int s = 0; s < 4; s++) {
        float4 f = wf4[4 * c + s];
        float o0 = r0.x * f.x + r0.y * f.y + r1.x * f.z + r1.y * f.w;
        float o1 = r0.z * f.x + r0.w * f.y + r1.z * f.z + r1.w * f.w;
        *(float2*)(dst + (size_t)s * BN * DIM * NPIX) = make_float2(o0, o1);
    }
}

// ---------------- attention precompute: conv -> QK^T -> softmax -> g_attn ----
// one CTA per (window, head); fully parallel (4096 CTAs)
#define A_LH  0                      // padded conv tile [32][145] = 4640
#define A_DWW 4640                   // 800
#define A_DWB 5440                   // 32
#define A_Q   5472                   // [64][33] = 2112
#define A_K   7584                   // [32][66] = 2112
#define A_TOT 9696

__global__ __launch_bounds__(256)
void wwa_attn(const float* __restrict__ dww, const float* __restrict__ dwb) {
    __shared__ float sm[A_TOT];
    const int t = threadIdx.x;
    const int wh = blockIdx.x;
    const int w = wh >> 3, i = wh & 7;
    const float* lhp = g_sub + ((size_t)BN + w) * DIM * NPIX + i * HD * NPIX;
    const float* hlp = g_sub + ((size_t)2 * BN + w) * DIM * NPIX + i * HD * NPIX;

    for (int k = t; k < 4640; k += 256) sm[A_LH + k] = 0.f;
    __syncthreads();
    for (int k = t; k < 2048; k += 256) {
        int c = k >> 6, n = k & 63;
        sm[A_LH + c * 145 + (n >> 3) * 12 + (n & 7) + 26] = lhp[k];  // (+2,+2) pad
        sm[A_K + c * 66 + n] = hlp[k];
    }
    for (int k = t; k < 800; k += 256) sm[A_DWW + k] = dww[i * 800 + k];
    if (t < 32) sm[A_DWB + t] = dwb[i * 32 + t];
    __syncthreads();

    // depthwise 5x5 conv (pad 2) -> q[n][d]
    {
        int d = t & 31, py = t >> 5;
        float wl[25];
#pragma unroll
        for (int k = 0; k < 25; k++) wl[k] = sm[A_DWW + d * 25 + k];
        float bb = sm[A_DWB + d];
        const float* base = &sm[A_LH + d * 145 + py * 12];
#pragma unroll
        for (int qx = 0; qx < 8; qx++) {
            float acc = bb;
#pragma unroll
            for (int ii = 0; ii < 5; ii++)
#pragma unroll
                for (int jj = 0; jj < 5; jj++)
                    acc += base[ii * 12 + qx + jj] * wl[ii * 5 + jj];
            sm[A_Q + (py * 8 + qx) * 33 + d] = acc;
        }
    }
    __syncthreads();

    // attn = softmax(q k^T * scale + bias) -> global
    {
        int rg = t >> 4, cg = t & 15, m0 = cg * 4;
        u64 acc[4][2] = {};
#pragma unroll 4
        for (int d = 0; d < 32; d++) {
            u64 k0 = *(const u64*)&sm[A_K + d * 66 + m0];
            u64 k1 = *(const u64*)&sm[A_K + d * 66 + m0 + 2];
#pragma unroll
            for (int r = 0; r < 4; r++) {
                float qv = sm[A_Q + (rg * 4 + r) * 33 + d];
                u64 q2 = pack2(qv, qv);
                fma2(acc[r][0], q2, k0);
                fma2(acc[r][1], q2, k1);
            }
        }
        float* ap = g_attn + (size_t)wh * 4096;
#pragma unroll
        for (int r = 0; r < 4; r++) {
            int n = rg * 4 + r;
            float v0, v1, v2, v3;
            unpack2(acc[r][0], v0, v1);
            unpack2(acc[r][1], v2, v3);
            const float4 bv = *(const float4*)&g_bias[i * 4096 + n * 64 + m0];
            v0 = v0 * ATTN_SCALE + bv.x; v1 = v1 * ATTN_SCALE + bv.y;
            v2 = v2 * ATTN_SCALE + bv.z; v3 = v3 * ATTN_SCALE + bv.w;
            float mx = fmaxf(fmaxf(v0, v1), fmaxf(v2, v3));
#pragma unroll
            for (int off = 8; off >= 1; off >>= 1)
                mx = fmaxf(mx, __shfl_xor_sync(0xffffffffu, mx, off));
            v0 = __expf(v0 - mx); v1 = __expf(v1 - mx);
            v2 = __expf(v2 - mx); v3 = __expf(v3 - mx);
            float s = v0 + v1 + v2 + v3;
#pragma unroll
            for (int off = 8; off >= 1; off >>= 1)
                s += __shfl_xor_sync(0xffffffffu, s, off);
            float inv = __fdividef(1.f, s);
            *(float4*)&ap[n * 64 + m0] = make_float4(v0 * inv, v1 * inv, v2 * inv, v3 * inv);
        }
    }
}

// ---------------- cascade + projection + inverse WT ----------------
// smem float offsets (dynamic, 103936 B total -> 2 CTAs/SM)
#define C_OUT 0                      // relu'd cat    [256][68] = 17408
#define C_V   17408                  // running v     [32][66]  =  2112
#define C_TMP 19520                  // raw attn out  [32][66]  =  2112
#define C_ATT 21632                  // attn tile     [64][68]  =  4352
#define C_TOT 25984
// sequential overlays of the V/TMP/ATT region (8576 floats at 17408):
#define C_W   17408                  // proj weight chunk [256][33] = 8448
// epilogue overlays (cat no longer needed): region [0..25984)
#define C_E   0                      // subband stage [3][256][9] = 6912
#define C_SO  6912                   // out stage     [256][33]   = 8448
#define SMEM_BYTES (C_TOT * 4)

__global__ __launch_bounds__(512, 2)
void wwa_casc(const float* __restrict__ pw, const float* __restrict__ pbias,
              const float* __restrict__ iwt, float* __restrict__ out) {
    extern __shared__ float sm[];
    const int t = threadIdx.x;
    const int w = blockIdx.x;
    const int b = w >> 8, wy = (w >> 4) & 15, wx = w & 15;
    const float* subw0 = g_sub + (size_t)w * DIM * NPIX;
    const float* subw1 = g_sub + ((size_t)BN + w) * DIM * NPIX;
    const float* subw2 = g_sub + ((size_t)2 * BN + w) * DIM * NPIX;
    const float* subw3 = g_sub + ((size_t)3 * BN + w) * DIM * NPIX;

#pragma unroll 1
    for (int i = 0; i < 8; i++) {
        __syncthreads();
        const float* ap = g_attn + (size_t)((w << 3) | i) * 4096;
        for (int k = t; k < 4096; k += 512) {
            int n = k >> 6, m = k & 63;
            sm[C_ATT + n * 68 + m] = ap[k];
        }
        const float* llp = subw0 + i * 2048;
        if (i == 0) {
            for (int k = t; k < 2048; k += 512) {
                int c = k >> 6, n = k & 63;
                sm[C_V + c * 66 + n] = llp[k];
            }
        } else {
            for (int k = t; k < 2048; k += 512) {
                int c = k >> 6, n = k & 63;
                sm[C_V + c * 66 + n] = sm[C_TMP + c * 66 + n] + llp[k];
            }
        }
        __syncthreads();

        // out[d][n] = sum_m v[d][m] * attn[n][m]
        int d = t & 31, n0 = (t >> 5) * 4;
        u64 acc[4] = {};
#pragma unroll 4
        for (int m = 0; m < 64; m += 4) {
            u64 v0 = *(const u64*)&sm[C_V + d * 66 + m];
            u64 v1 = *(const u64*)&sm[C_V + d * 66 + m + 2];
#pragma unroll
            for (int j = 0; j < 4; j++) {
                longlong2 a2 = *(const longlong2*)&sm[C_ATT + (n0 + j) * 68 + m];
                fma2(acc[j], v0, (u64)a2.x);
                fma2(acc[j], v1, (u64)a2.y);
            }
        }
#pragma unroll
        for (int j = 0; j < 4; j++) {
            float lo, hi; unpack2(acc[j], lo, hi);
            float val = lo + hi;
            sm[C_TMP + d * 66 + n0 + j] = val;
            sm[C_OUT + (i * 32 + d) * 68 + n0 + j] = fmaxf(val, 0.f);
        }
    }
    __syncthreads();

    // --- projection: o = t&255, half = t>>8 covers 32 pixels (16 u64) ---
    const int o = t & 255, half = t >> 8;
    u64 acc[16];
    {
        float pbv = pbias[o];
        u64 pi = pack2(pbv, pbv);
#pragma unroll
        for (int u = 0; u < 16; u++) acc[u] = pi;
    }
#pragma unroll 1
    for (int cc = 0; cc < 256; cc += 32) {
        __syncthreads();
        for (int k = t; k < 8192; k += 512) {
            int oo = k >> 5, c = k & 31;
            sm[C_W + oo * 33 + c] = pw[oo * 256 + cc + c];
        }
        __syncthreads();
#pragma unroll 4
        for (int c2 = 0; c2 < 32; c2++) {
            float wv = sm[C_W + o * 33 + c2];
            u64 w2 = pack2(wv, wv);
            const longlong2* row = (const longlong2*)&sm[C_OUT + (cc + c2) * 68 + half * 32];
#pragma unroll
            for (int u = 0; u < 8; u++) {
                longlong2 p = row[u];
                fma2(acc[2 * u],     w2, (u64)p.x);
                fma2(acc[2 * u + 1], w2, (u64)p.y);
            }
        }
    }

    // --- inverse WT epilogue, staged for coalescing ---
    const float4* iw4 = (const float4*)iwt;
    float4 f0 = iw4[4 * o + 0], f1 = iw4[4 * o + 1];
    float4 f2 = iw4[4 * o + 2], f3 = iw4[4 * o + 3];
    float* ob = out + (size_t)(b * DIM) * RES * RES;
    const int ybase = wy * 16, xbase = wx * 16;

#pragma unroll 1
    for (int ch = 0; ch < 8; ch++) {
        __syncthreads();
        // stage lh/hl/hh for pixels n = h*32 + 4*ch + pp (h=0,1; pp=0..3), all 256 o
        for (int k = t; k < 6144; k += 512) {
            int arr = k >> 11, r = k & 2047;
            int oo = r >> 3, p = r & 7;
            int hh = p >> 2, pp = p & 3;
            int n = hh * 32 + 4 * ch + pp;
            const float* src = (arr == 0) ? subw1 : (arr == 1) ? subw2 : subw3;
            sm[C_E + arr * 2304 + oo * 9 + p] = src[oo * 64 + n];
        }
        __syncthreads();
        // compute 16 outputs per thread -> s_o[o][half*16 + jj]
        {
            float av[4];
            unpack2(acc[2 * ch],     av[0], av[1]);
            unpack2(acc[2 * ch + 1], av[2], av[3]);
#pragma unroll
            for (int pp = 0; pp < 4; pp++) {
                float a  = av[pp];
                float lh = sm[C_E + 0 * 2304 + o * 9 + half * 4 + pp];
                float hl = sm[C_E + 1 * 2304 + o * 9 + half * 4 + pp];
                float hh = sm[C_E + 2 * 2304 + o * 9 + half * 4 + pp];
                float o00 = a * f0.x + lh * f1.x + hl * f2.x + hh * f3.x;
                float o01 = a * f0.y + lh * f1.y + hl * f2.y + hh * f3.y;
                float o10 = a * f0.z + lh * f1.z + hl * f2.z + hh * f3.z;
                float o11 = a * f0.w + lh * f1.w + hl * f2.w + hh * f3.w;
                int jb = half * 16 + pp * 2;
                sm[C_SO + o * 33 + jb + 0] = o00;
                sm[C_SO + o * 33 + jb + 1] = o01;
                sm[C_SO + o * 33 + jb + 8] = o10;
                sm[C_SO + o * 33 + jb + 9] = o11;
            }
        }
        __syncthreads();
        // coalesced store: 32 outputs per o
        for (int k = t; k < 8192; k += 512) {
            int oo = k >> 5, j = k & 31;
            int hh = j >> 4, jj = j & 15;
            int py = 4 * hh + (ch >> 1);
            int y = ybase + 2 * py + (jj >> 3);
            int x = xbase + 2 * ((ch & 1) * 4) + (jj & 7);
            ob[(size_t)oo * RES * RES + (size_t)y * RES + x] = sm[C_SO + oo * 33 + hh * 16 + jj];
        }
    }
}

extern "C" void kernel_launch(void* const* d_in, const int* in_sizes, int n_in,
                              void* d_out, int out_size) {
    const float* x    = (const float*)d_in[0];
    const float* wtf  = (const float*)d_in[1];
    const float* iwtf = (const float*)d_in[2];
    const float* dww  = (const float*)d_in[3];
    const float* dwb  = (const float*)d_in[4];
    const float* pw   = (const float*)d_in[5];
    const float* pb   = (const float*)d_in[6];
    const float* ab   = (const float*)d_in[7];
    const int*   idxs = (const int*)d_in[8];
    int n_off = in_sizes[7] / HEADS;
    float* out = (float*)d_out;

    cudaFuncSetAttribute(wwa_casc, cudaFuncAttributeMaxDynamicSharedMemorySize, SMEM_BYTES);

    wwa_bias<<<128, 256>>>(ab, idxs, n_off);
    wwa_wt<<<16384, 256>>>(x, wtf);
    wwa_attn<<<BN * HEADS, 256>>>(dww, dwb);
    wwa_casc<<<BN, 512, SMEM_BYTES>>>(pw, pb, iwtf, out);
}